// round 3
// baseline (speedup 1.0000x reference)
#include <cuda_runtime.h>
#include <cuda_bf16.h>
#include <cstdint>

// Problem constants
#define BATCH   2048
#define SEQ     32
#define EMB     1024
#define HEADS   16
#define HSIZE   64
#define BT      (BATCH * SEQ)          // 65536 rows
#define QKV_N   (3 * EMB)              // 3072

// ---------------------------------------------------------------------------
// Scratch (device globals; no dynamic allocation allowed)
// ---------------------------------------------------------------------------
__device__ float g_qkv[(size_t)BT * QKV_N];      // [65536, 3072] : Q | K | V
__device__ float g_y[(size_t)BT * EMB];          // [65536, 1024] : concat heads
__device__ float g_wpack[(size_t)EMB * QKV_N];   // [1024, 3072]  : packed weights

// ---------------------------------------------------------------------------
// Kernel 0: pack Wq/Wk/Wv [H, E, HS] into row-major [E, 3*E]
//   col j: section s = j/1024 (0=Q,1=K,2=V), n = j%1024, h = n/64, d = n%64
//   wpack[e, j] = W_s[h, e, d]
// ---------------------------------------------------------------------------
__global__ void pack_w_kernel(const float* __restrict__ Wq,
                              const float* __restrict__ Wk,
                              const float* __restrict__ Wv,
                              float* __restrict__ out) {
    int idx = blockIdx.x * 256 + threadIdx.x;
    if (idx >= EMB * QKV_N) return;
    int e = idx / QKV_N;
    int j = idx - e * QKV_N;
    int s = j >> 10;           // 0,1,2
    int n = j & 1023;
    int h = n >> 6;
    int d = n & 63;
    const float* W = (s == 0) ? Wq : ((s == 1) ? Wk : Wv);
    out[idx] = W[((size_t)h * EMB + e) * HSIZE + d];
}

// ---------------------------------------------------------------------------
// SGEMM: C[M,N] = A[M,K] * B[K,N] (+ bias[N] if bias != nullptr)
// BM=BN=128, BK=16, 256 threads, 8x8 per thread (split 4+4 rows/cols).
// M % 128 == 0, N % 128 == 0, K % 16 == 0 guaranteed by problem shapes.
// ---------------------------------------------------------------------------
#define BM 128
#define BN 128
#define BK 16

__global__ __launch_bounds__(256, 2)
void sgemm_kernel(const float* __restrict__ A,
                  const float* __restrict__ B,
                  float* __restrict__ C,
                  const float* __restrict__ bias,
                  int N, int K) {
    __shared__ float As[BK][BM];
    __shared__ float Bs[BK][BN];

    const int tid = threadIdx.x;
    const int bn  = blockIdx.x;
    const int bm  = blockIdx.y;

    const float* Ab = A + (size_t)bm * BM * K;
    const float* Bb = B + (size_t)bn * BN;

    const int tn = tid & 15;   // 0..15
    const int tm = tid >> 4;   // 0..15

    float acc[8][8];
#pragma unroll
    for (int i = 0; i < 8; i++)
#pragma unroll
        for (int j = 0; j < 8; j++) acc[i][j] = 0.f;

    for (int k0 = 0; k0 < K; k0 += BK) {
        // Load A tile [128 x 16] -> transposed As[k][m]
#pragma unroll
        for (int it = 0; it < 2; it++) {
            int id   = tid + it * 256;   // 0..511 float4 slots
            int row  = id >> 2;          // 0..127
            int col4 = id & 3;           // 0..3
            float4 v = *(const float4*)(Ab + (size_t)row * K + k0 + col4 * 4);
            As[col4 * 4 + 0][row] = v.x;
            As[col4 * 4 + 1][row] = v.y;
            As[col4 * 4 + 2][row] = v.z;
            As[col4 * 4 + 3][row] = v.w;
        }
        // Load B tile [16 x 128] row-major
#pragma unroll
        for (int it = 0; it < 2; it++) {
            int id   = tid + it * 256;
            int row  = id >> 5;          // 0..15
            int col4 = id & 31;          // 0..31
            float4 v = *(const float4*)(Bb + (size_t)(k0 + row) * N + col4 * 4);
            *(float4*)&Bs[row][col4 * 4] = v;
        }
        __syncthreads();

#pragma unroll
        for (int kk = 0; kk < BK; kk++) {
            float a[8], b[8];
            float4 a0 = *(const float4*)&As[kk][tm * 4];
            float4 a1 = *(const float4*)&As[kk][64 + tm * 4];
            float4 b0 = *(const float4*)&Bs[kk][tn * 4];
            float4 b1 = *(const float4*)&Bs[kk][64 + tn * 4];
            a[0] = a0.x; a[1] = a0.y; a[2] = a0.z; a[3] = a0.w;
            a[4] = a1.x; a[5] = a1.y; a[6] = a1.z; a[7] = a1.w;
            b[0] = b0.x; b[1] = b0.y; b[2] = b0.z; b[3] = b0.w;
            b[4] = b1.x; b[5] = b1.y; b[6] = b1.z; b[7] = b1.w;
#pragma unroll
            for (int i = 0; i < 8; i++)
#pragma unroll
                for (int j = 0; j < 8; j++)
                    acc[i][j] += a[i] * b[j];
        }
        __syncthreads();
    }

    // Epilogue: rows {tm*4..+3, 64+tm*4..+3}, cols {tn*4..+3, 64+tn*4..+3}
    const int row0 = bm * BM + tm * 4;
    const int col0 = bn * BN + tn * 4;

    float bv[8];
#pragma unroll
    for (int j = 0; j < 8; j++) {
        int c = col0 + ((j < 4) ? j : (64 + j - 4));
        bv[j] = bias ? bias[c] : 0.f;
    }

#pragma unroll
    for (int ih = 0; ih < 2; ih++) {
#pragma unroll
        for (int i = 0; i < 4; i++) {
            int r = row0 + ih * 64 + i;
            float* crow = C + (size_t)r * N;
            float4 v0, v1;
            v0.x = acc[ih * 4 + i][0] + bv[0];
            v0.y = acc[ih * 4 + i][1] + bv[1];
            v0.z = acc[ih * 4 + i][2] + bv[2];
            v0.w = acc[ih * 4 + i][3] + bv[3];
            v1.x = acc[ih * 4 + i][4] + bv[4];
            v1.y = acc[ih * 4 + i][5] + bv[5];
            v1.z = acc[ih * 4 + i][6] + bv[6];
            v1.w = acc[ih * 4 + i][7] + bv[7];
            *(float4*)(crow + col0)      = v0;
            *(float4*)(crow + col0 + 64) = v1;
        }
    }
}

// ---------------------------------------------------------------------------
// Attention core: one block per (batch, head). 128 threads.
// qkv: [BT, 3072] (Q|K|V per row). y: [BT, 1024] head-concat output.
// ---------------------------------------------------------------------------
__global__ __launch_bounds__(128)
void attn_kernel(const float* __restrict__ qkv, float* __restrict__ y) {
    __shared__ float qs[SEQ][HSIZE + 1];
    __shared__ float ks[SEQ][HSIZE + 1];
    __shared__ float vs[SEQ][HSIZE + 1];
    __shared__ float ss[SEQ][SEQ + 1];

    const int bh = blockIdx.x;
    const int b  = bh >> 4;
    const int h  = bh & 15;
    const int tid = threadIdx.x;

    const float* base = qkv + (size_t)b * SEQ * QKV_N + h * HSIZE;

    // Load q, k, v tiles (coalesced: consecutive tid -> consecutive d)
    for (int idx = tid; idx < SEQ * HSIZE; idx += 128) {
        int t = idx >> 6;
        int d = idx & 63;
        const float* rp = base + (size_t)t * QKV_N + d;
        qs[t][d] = rp[0];
        ks[t][d] = rp[EMB];
        vs[t][d] = rp[2 * EMB];
    }
    __syncthreads();

    // Scores (lower triangle only), scale by 1/sqrt(64) = 0.125
    for (int e = tid; e < SEQ * SEQ; e += 128) {
        int i = e >> 5;
        int j = e & 31;
        float acc = 0.f;
        if (j <= i) {
#pragma unroll
            for (int d = 0; d < HSIZE; d++) acc += qs[i][d] * ks[j][d];
            acc *= 0.125f;
        }
        ss[i][j] = acc;
    }
    __syncthreads();

    // Causal softmax: one thread per row (rows are tiny)
    if (tid < SEQ) {
        const int i = tid;
        float mx = -1e30f;
        for (int j = 0; j <= i; j++) mx = fmaxf(mx, ss[i][j]);
        float sum = 0.f;
        for (int j = 0; j <= i; j++) {
            float ev = __expf(ss[i][j] - mx);
            ss[i][j] = ev;
            sum += ev;
        }
        float inv = 1.f / sum;
        for (int j = 0; j <= i; j++) ss[i][j] *= inv;
        for (int j = i + 1; j < SEQ; j++) ss[i][j] = 0.f;
    }
    __syncthreads();

    // out = att @ v, write head-concat output
    for (int idx = tid; idx < SEQ * HSIZE; idx += 128) {
        int i = idx >> 6;
        int d = idx & 63;
        float acc = 0.f;
#pragma unroll
        for (int j = 0; j < SEQ; j++) acc += ss[i][j] * vs[j][d];
        y[((size_t)b * SEQ + i) * EMB + h * HSIZE + d] = acc;
    }
}

// ---------------------------------------------------------------------------
// Launch
// ---------------------------------------------------------------------------
extern "C" void kernel_launch(void* const* d_in, const int* in_sizes, int n_in,
                              void* d_out, int out_size) {
    const float* x  = (const float*)d_in[0];   // [2048, 32, 1024]
    const float* Wq = (const float*)d_in[1];   // [16, 1024, 64]
    const float* Wk = (const float*)d_in[2];
    const float* Wv = (const float*)d_in[3];
    const float* Wp = (const float*)d_in[4];   // [1024, 1024]
    const float* bp = (const float*)d_in[5];   // [1024]
    float* out = (float*)d_out;                // [2048, 32, 1024]

    float* qkv;  cudaGetSymbolAddress((void**)&qkv,  g_qkv);
    float* yb;   cudaGetSymbolAddress((void**)&yb,   g_y);
    float* wpk;  cudaGetSymbolAddress((void**)&wpk,  g_wpack);

    // 0. Pack QKV weights into [1024, 3072]
    {
        int total = EMB * QKV_N;
        pack_w_kernel<<<(total + 255) / 256, 256>>>(Wq, Wk, Wv, wpk);
    }
    // 1. QKV projection: [65536,1024] x [1024,3072]
    {
        dim3 grid(QKV_N / BN, BT / BM);
        sgemm_kernel<<<grid, 256>>>(x, wpk, qkv, nullptr, QKV_N, EMB);
    }
    // 2. Attention per (b, h)
    attn_kernel<<<BATCH * HEADS, 128>>>(qkv, yb);
    // 3. Output projection + bias: [65536,1024] x [1024,1024]
    {
        dim3 grid(EMB / BN, BT / BM);
        sgemm_kernel<<<grid, 256>>>(yb, Wp, out, bp, EMB, EMB);
    }
}